// round 1
// baseline (speedup 1.0000x reference)
#include <cuda_runtime.h>
#include <cuda_bf16.h>
#include <math.h>

#define BS 2
#define NQ 10000
#define NV 19560
#define EMBED 256
#define NHEAD 8
#define HDIM 32
#define NLVL 4
#define NPTS 4

// Scratch (allocation-free rule: __device__ globals)
__device__ float g_v[(size_t)BS * NV * EMBED];      // value @ W_val + b_val, (b, pos, h, d)
__device__ float g_off[(size_t)BS * NQ * 256];      // sampling offsets raw
__device__ float g_attn[(size_t)BS * NQ * 128];     // attn logits

// ---------------------------------------------------------------------------
// Generic fp32 GEMM: C[M,N] = (A + A2?) @ W[K,N] + bias[N]
// 64x64 tile, BK=16, 256 threads, 4x4 microtile per thread.
// ---------------------------------------------------------------------------
#define BM 64
#define BN 64
#define BK 16

__global__ void gemm_bias_kernel(const float* __restrict__ A,
                                 const float* __restrict__ A2,
                                 const float* __restrict__ W,
                                 const float* __restrict__ bias,
                                 float* __restrict__ C,
                                 int M, int N, int K)
{
    __shared__ float As[BK][BM];
    __shared__ float Bs[BK][BN];

    const int tid = threadIdx.x;
    const int m0 = blockIdx.y * BM;
    const int n0 = blockIdx.x * BN;
    const int tx = tid & 15;        // 0..15 -> 4 cols each
    const int ty = tid >> 4;        // 0..15 -> 4 rows each

    float acc[4][4] = {};

    const int arow  = tid >> 2;          // 0..63
    const int acol4 = (tid & 3) * 4;     // 0,4,8,12
    const int brow  = tid >> 4;          // 0..15
    const int bcol4 = (tid & 15) * 4;    // 0..60

    for (int k0 = 0; k0 < K; k0 += BK) {
        // load A tile (64 x 16), fold in A2 if present
        float4 av = make_float4(0.f, 0.f, 0.f, 0.f);
        const int gm = m0 + arow;
        if (gm < M) {
            av = *(const float4*)(A + (size_t)gm * K + k0 + acol4);
            if (A2) {
                float4 a2 = *(const float4*)(A2 + (size_t)gm * K + k0 + acol4);
                av.x += a2.x; av.y += a2.y; av.z += a2.z; av.w += a2.w;
            }
        }
        As[acol4 + 0][arow] = av.x;
        As[acol4 + 1][arow] = av.y;
        As[acol4 + 2][arow] = av.z;
        As[acol4 + 3][arow] = av.w;

        // load B tile (16 x 64)
        float4 bv = *(const float4*)(W + (size_t)(k0 + brow) * N + n0 + bcol4);
        *(float4*)&Bs[brow][bcol4] = bv;

        __syncthreads();

#pragma unroll
        for (int k = 0; k < BK; k++) {
            float a[4], b[4];
#pragma unroll
            for (int i = 0; i < 4; i++) a[i] = As[k][ty * 4 + i];
#pragma unroll
            for (int j = 0; j < 4; j++) b[j] = Bs[k][tx * 4 + j];
#pragma unroll
            for (int i = 0; i < 4; i++)
#pragma unroll
                for (int j = 0; j < 4; j++)
                    acc[i][j] = fmaf(a[i], b[j], acc[i][j]);
        }
        __syncthreads();
    }

    const int gn = n0 + tx * 4;
    float4 bsv = *(const float4*)(bias + gn);
#pragma unroll
    for (int i = 0; i < 4; i++) {
        const int gm = m0 + ty * 4 + i;
        if (gm < M) {
            float4 o;
            o.x = acc[i][0] + bsv.x;
            o.y = acc[i][1] + bsv.y;
            o.z = acc[i][2] + bsv.z;
            o.w = acc[i][3] + bsv.w;
            *(float4*)(C + (size_t)gm * N + gn) = o;
        }
    }
}

// ---------------------------------------------------------------------------
// Deformable sampling: one warp per (b, q, head); lane = channel d (HDIM==32).
// Lanes 0..15 own the 16 (level, point) slots: softmax + coordinate math,
// then broadcast each slot via shfl; every lane gathers its channel from the
// 4 bilinear corners (each corner = one coalesced 128B line from g_v in L2).
// ---------------------------------------------------------------------------
__global__ void sample_kernel(const float* __restrict__ refpts,
                              float* __restrict__ out)
{
    const int gwarp = (blockIdx.x * blockDim.x + threadIdx.x) >> 5;
    const int lane = threadIdx.x & 31;
    const int total = BS * NQ * NHEAD;
    if (gwarp >= total) return;

    const int h  = gwarp & (NHEAD - 1);
    const int bq = gwarp >> 3;            // b*NQ + q
    const int b  = bq / NQ;

    const unsigned FULL = 0xFFFFFFFFu;

    // ---- softmax over 16 (level,point) slots ----
    float a = -INFINITY;
    if (lane < 16) a = g_attn[(size_t)bq * 128 + h * 16 + lane];
    float amax = a;
#pragma unroll
    for (int s = 16; s > 0; s >>= 1)
        amax = fmaxf(amax, __shfl_xor_sync(FULL, amax, s));
    float e = (lane < 16) ? __expf(a - amax) : 0.f;
    float esum = e;
#pragma unroll
    for (int s = 16; s > 0; s >>= 1)
        esum += __shfl_xor_sync(FULL, esum, s);
    const float wgt = e / esum;

    // ---- per-slot sampling coordinates (lanes 0..15) ----
    const float LW[4] = {160.f, 80.f, 40.f, 20.f};
    const float LH[4] = {92.f, 46.f, 23.f, 12.f};

    float x = 0.f, y = 0.f;
    if (lane < 16) {
        const int l  = lane >> 2;
        const int pt = lane & 3;
        const float offx = g_off[(size_t)bq * 256 + h * 32 + l * 8 + pt * 2 + 0];
        const float offy = g_off[(size_t)bq * 256 + h * 32 + l * 8 + pt * 2 + 1];
        const float rx = refpts[(size_t)bq * 8 + pt * 2 + 0];
        const float ry = refpts[(size_t)bq * 8 + pt * 2 + 1];
        const float locx = rx + offx / LW[l];
        const float locy = ry + offy / LH[l];
        x = fmaf(locx, LW[l], -0.5f);
        y = fmaf(locy, LH[l], -0.5f);
    }

    const int HH[4] = {92, 46, 23, 12};
    const int WW[4] = {160, 80, 40, 20};
    const int ST[4] = {0, 14720, 18400, 19320};

    float acc = 0.f;
    const size_t vbase_b = (size_t)b * NV;

#pragma unroll
    for (int p = 0; p < 16; p++) {
        const float xp = __shfl_sync(FULL, x, p);
        const float yp = __shfl_sync(FULL, y, p);
        const float wp = __shfl_sync(FULL, wgt, p);
        const int l = p >> 2;
        const int Hl = HH[l], Wl = WW[l], base = ST[l];

        const float x0f = floorf(xp), y0f = floorf(yp);
        const float wx1 = xp - x0f, wy1 = yp - y0f;
        const float wx0 = 1.f - wx1, wy0 = 1.f - wy1;
        const int x0 = (int)x0f, y0 = (int)y0f;

        float s = 0.f;
#pragma unroll
        for (int cy = 0; cy < 2; cy++) {
#pragma unroll
            for (int cx = 0; cx < 2; cx++) {
                const int yy = y0 + cy;
                const int xx = x0 + cx;
                if (yy >= 0 && yy < Hl && xx >= 0 && xx < Wl) {
                    const size_t idx =
                        ((vbase_b + base + (size_t)yy * Wl + xx) * NHEAD + h) * HDIM + lane;
                    const float cw = (cy ? wy1 : wy0) * (cx ? wx1 : wx0);
                    s = fmaf(__ldg(&g_v[idx]), cw, s);
                }
            }
        }
        acc = fmaf(wp, s, acc);
    }

    out[(size_t)bq * EMBED + h * HDIM + lane] = acc;
}

// ---------------------------------------------------------------------------
extern "C" void kernel_launch(void* const* d_in, const int* in_sizes, int n_in,
                              void* d_out, int out_size)
{
    const float* query   = (const float*)d_in[0];
    const float* value   = (const float*)d_in[1];
    const float* qpos    = (const float*)d_in[2];
    const float* refpts  = (const float*)d_in[3];
    const float* W_val   = (const float*)d_in[4];
    const float* b_val   = (const float*)d_in[5];
    const float* W_off   = (const float*)d_in[6];
    const float* b_off   = (const float*)d_in[7];
    const float* W_attn  = (const float*)d_in[8];
    const float* b_attn  = (const float*)d_in[9];
    float* out = (float*)d_out;

    float *pv, *poff, *pattn;
    cudaGetSymbolAddress((void**)&pv, g_v);
    cudaGetSymbolAddress((void**)&poff, g_off);
    cudaGetSymbolAddress((void**)&pattn, g_attn);

    const int Mv = BS * NV;      // 39120
    const int Mq = BS * NQ;      // 20000

    // value projection: g_v = value @ W_val + b_val
    {
        dim3 grid(EMBED / BN, (Mv + BM - 1) / BM);
        gemm_bias_kernel<<<grid, 256>>>(value, nullptr, W_val, b_val, pv,
                                        Mv, EMBED, EMBED);
    }
    // offsets: g_off = (query + qpos) @ W_off + b_off
    {
        dim3 grid(256 / BN, (Mq + BM - 1) / BM);
        gemm_bias_kernel<<<grid, 256>>>(query, qpos, W_off, b_off, poff,
                                        Mq, 256, EMBED);
    }
    // attn logits: g_attn = (query + qpos) @ W_attn + b_attn
    {
        dim3 grid(128 / BN, (Mq + BM - 1) / BM);
        gemm_bias_kernel<<<grid, 256>>>(query, qpos, W_attn, b_attn, pattn,
                                        Mq, 128, EMBED);
    }
    // sampling + weighted sum
    {
        const int total_warps = BS * NQ * NHEAD;     // 160000
        const int warps_per_block = 8;
        const int blocks = (total_warps + warps_per_block - 1) / warps_per_block;
        sample_kernel<<<blocks, warps_per_block * 32>>>(refpts, out);
    }
}

// round 2
// speedup vs baseline: 1.0097x; 1.0097x over previous
#include <cuda_runtime.h>
#include <cuda_bf16.h>
#include <math.h>

#define BS 2
#define NQ 10000
#define NV 19560
#define EMBED 256
#define NHEAD 8
#define HDIM 32

typedef unsigned long long ull;

// Scratch (allocation-free rule: __device__ globals)
__device__ float g_v[(size_t)BS * NHEAD * NV * HDIM]; // (b, h, pos, d)
__device__ float g_off[(size_t)BS * NQ * 256];        // sampling offsets raw
__device__ float g_attn[(size_t)BS * NQ * 128];       // attn logits

// ---------------------------------------------------------------------------
// Packed-f32x2 GEMM: C[M,N] = (A + A2?) @ W[K,N] + bias[N]
// 128x128 tile, BK=16, 256 threads, 8x8 microtile, accumulators packed along N.
// A is stored duplicated (a,a) in SMEM so inner loop is pure LDS.128 + FFMA2.
// If permuteV != 0, C is written in (b, h, pos, d) layout instead of row-major.
// ---------------------------------------------------------------------------
#define GBM 128
#define GBN 128
#define GBK 16

__device__ __forceinline__ void ffma2(ull& d, ull a, ull b) {
    asm("fma.rn.f32x2 %0, %1, %2, %0;" : "+l"(d) : "l"(a), "l"(b));
}

__global__ __launch_bounds__(256, 2)
void gemm2_kernel(const float* __restrict__ A,
                  const float* __restrict__ A2,
                  const float* __restrict__ W,
                  const float* __restrict__ bias,
                  float* __restrict__ C,
                  int M, int N, int K, int permuteV)
{
    __shared__ float2 As2[GBK][GBM];   // duplicated pairs (a,a)
    __shared__ float  Bs[GBK][GBN];

    const int tid = threadIdx.x;
    const int m0 = blockIdx.y * GBM;
    const int n0 = blockIdx.x * GBN;

    // global load mapping
    const int arow  = tid >> 1;          // 0..127
    const int acol  = (tid & 1) * 8;     // 0 or 8
    const int brow  = tid >> 4;          // 0..15
    const int bcol  = (tid & 15) * 8;    // 0..120

    // microtile mapping: 16x16 thread grid, 8 rows x 8 cols each
    const int ty = tid >> 4;
    const int tx = tid & 15;

    ull acc[8][4];
#pragma unroll
    for (int i = 0; i < 8; i++)
#pragma unroll
        for (int j = 0; j < 4; j++) acc[i][j] = 0ull;

    for (int k0 = 0; k0 < K; k0 += GBK) {
        // ---- A tile: clamp row so OOB rows read valid memory (results unused)
        {
            int gm = m0 + arow;
            if (gm >= M) gm = M - 1;
            const float* ap = A + (size_t)gm * K + k0 + acol;
            float4 v0 = *(const float4*)(ap);
            float4 v1 = *(const float4*)(ap + 4);
            if (A2) {
                const float* a2p = A2 + (size_t)gm * K + k0 + acol;
                float4 u0 = *(const float4*)(a2p);
                float4 u1 = *(const float4*)(a2p + 4);
                v0.x += u0.x; v0.y += u0.y; v0.z += u0.z; v0.w += u0.w;
                v1.x += u1.x; v1.y += u1.y; v1.z += u1.z; v1.w += u1.w;
            }
            As2[acol + 0][arow] = make_float2(v0.x, v0.x);
            As2[acol + 1][arow] = make_float2(v0.y, v0.y);
            As2[acol + 2][arow] = make_float2(v0.z, v0.z);
            As2[acol + 3][arow] = make_float2(v0.w, v0.w);
            As2[acol + 4][arow] = make_float2(v1.x, v1.x);
            As2[acol + 5][arow] = make_float2(v1.y, v1.y);
            As2[acol + 6][arow] = make_float2(v1.z, v1.z);
            As2[acol + 7][arow] = make_float2(v1.w, v1.w);
        }
        // ---- B tile
        {
            const float* wp = W + (size_t)(k0 + brow) * N + n0 + bcol;
            *(float4*)&Bs[brow][bcol]     = *(const float4*)(wp);
            *(float4*)&Bs[brow][bcol + 4] = *(const float4*)(wp + 4);
        }
        __syncthreads();

#pragma unroll
        for (int k = 0; k < GBK; k++) {
            ull a[8], b[4];
            const ulonglong2* ap = (const ulonglong2*)&As2[k][ty * 8];
#pragma unroll
            for (int i = 0; i < 4; i++) {
                ulonglong2 t = ap[i];
                a[i * 2] = t.x; a[i * 2 + 1] = t.y;
            }
            const ulonglong2* bp = (const ulonglong2*)&Bs[k][tx * 8];
            ulonglong2 t0 = bp[0], t1 = bp[1];
            b[0] = t0.x; b[1] = t0.y; b[2] = t1.x; b[3] = t1.y;
#pragma unroll
            for (int i = 0; i < 8; i++)
#pragma unroll
                for (int j = 0; j < 4; j++)
                    ffma2(acc[i][j], a[i], b[j]);
        }
        __syncthreads();
    }

    // ---- epilogue
    const int gn = n0 + tx * 8;
    float4 bs0 = *(const float4*)(bias + gn);
    float4 bs1 = *(const float4*)(bias + gn + 4);

#pragma unroll
    for (int i = 0; i < 8; i++) {
        const int gm = m0 + ty * 8 + i;
        if (gm >= M) break;
        float r[8];
#pragma unroll
        for (int j = 0; j < 4; j++) {
            float2 v = *(float2*)&acc[i][j];
            r[j * 2] = v.x; r[j * 2 + 1] = v.y;
        }
        r[0] += bs0.x; r[1] += bs0.y; r[2] += bs0.z; r[3] += bs0.w;
        r[4] += bs1.x; r[5] += bs1.y; r[6] += bs1.z; r[7] += bs1.w;

        float* dst;
        if (permuteV) {
            const int b = gm / NV;
            const int pos = gm - b * NV;
            const int h = gn >> 5;         // 8 cols stay within one head
            const int d = gn & 31;
            dst = C + (((size_t)(b * NHEAD + h) * NV + pos) * HDIM + d);
        } else {
            dst = C + (size_t)gm * N + gn;
        }
        *(float4*)(dst)     = make_float4(r[0], r[1], r[2], r[3]);
        *(float4*)(dst + 4) = make_float4(r[4], r[5], r[6], r[7]);
    }
}

// ---------------------------------------------------------------------------
// Deformable sampling: one warp per (b, q, head); lane = channel d (HDIM==32).
// g_v layout (b, h, pos, d): one base pointer per warp, 32-bit position index.
// ---------------------------------------------------------------------------
__global__ void sample_kernel(const float* __restrict__ refpts,
                              float* __restrict__ out)
{
    const int gwarp = (blockIdx.x * blockDim.x + threadIdx.x) >> 5;
    const int lane = threadIdx.x & 31;
    const int total = BS * NQ * NHEAD;
    if (gwarp >= total) return;

    const int h  = gwarp & (NHEAD - 1);
    const int bq = gwarp >> 3;            // b*NQ + q
    const int b  = bq / NQ;

    const unsigned FULL = 0xFFFFFFFFu;

    // ---- softmax over 16 (level,point) slots ----
    float a = -INFINITY;
    if (lane < 16) a = g_attn[(size_t)bq * 128 + h * 16 + lane];
    float amax = a;
#pragma unroll
    for (int s = 16; s > 0; s >>= 1)
        amax = fmaxf(amax, __shfl_xor_sync(FULL, amax, s));
    float e = (lane < 16) ? __expf(a - amax) : 0.f;
    float esum = e;
#pragma unroll
    for (int s = 16; s > 0; s >>= 1)
        esum += __shfl_xor_sync(FULL, esum, s);
    const float wgt = e / esum;

    // ---- per-slot pixel coordinates (lanes 0..15) ----
    const float LW[4] = {160.f, 80.f, 40.f, 20.f};
    const float LH[4] = {92.f, 46.f, 23.f, 12.f};

    float x = 0.f, y = 0.f;
    if (lane < 16) {
        const int l  = lane >> 2;
        const int pt = lane & 3;
        const float offx = g_off[(size_t)bq * 256 + h * 32 + l * 8 + pt * 2 + 0];
        const float offy = g_off[(size_t)bq * 256 + h * 32 + l * 8 + pt * 2 + 1];
        const float rx = refpts[(size_t)bq * 8 + pt * 2 + 0];
        const float ry = refpts[(size_t)bq * 8 + pt * 2 + 1];
        const float locx = rx + offx / LW[l];
        const float locy = ry + offy / LH[l];
        x = fmaf(locx, LW[l], -0.5f);
        y = fmaf(locy, LH[l], -0.5f);
    }

    const int HH[4] = {92, 46, 23, 12};
    const int WW[4] = {160, 80, 40, 20};
    const int ST[4] = {0, 14720, 18400, 19320};

    // base pointer for this (b, h) plane; lane adds channel offset
    const float* __restrict__ vp =
        g_v + ((size_t)(b * NHEAD + h) * NV) * HDIM + lane;

    float acc = 0.f;

#pragma unroll
    for (int p = 0; p < 16; p++) {
        const float xp = __shfl_sync(FULL, x, p);
        const float yp = __shfl_sync(FULL, y, p);
        const float wp = __shfl_sync(FULL, wgt, p);
        const int l = p >> 2;
        const int Hl = HH[l], Wl = WW[l], base = ST[l];

        const float x0f = floorf(xp), y0f = floorf(yp);
        const float wx1 = xp - x0f;
        const float wy1r = yp - y0f;
        const float wx0 = 1.f - wx1;
        const float wy1 = wy1r * wp;          // fold softmax weight in
        const float wy0 = (1.f - wy1r) * wp;
        const int x0 = (int)x0f, y0 = (int)y0f;

        const int idx00 = (base + y0 * Wl + x0) * HDIM;
        const bool vx0 = (unsigned)x0 < (unsigned)Wl;
        const bool vx1 = (unsigned)(x0 + 1) < (unsigned)Wl;
        const bool vy0 = (unsigned)y0 < (unsigned)Hl;
        const bool vy1 = (unsigned)(y0 + 1) < (unsigned)Hl;
        const int rstep = Wl * HDIM;

        if (vy0 & vx0) acc = fmaf(__ldg(vp + idx00),              wy0 * wx0, acc);
        if (vy0 & vx1) acc = fmaf(__ldg(vp + idx00 + HDIM),       wy0 * wx1, acc);
        if (vy1 & vx0) acc = fmaf(__ldg(vp + idx00 + rstep),      wy1 * wx0, acc);
        if (vy1 & vx1) acc = fmaf(__ldg(vp + idx00 + rstep + HDIM), wy1 * wx1, acc);
    }

    out[(size_t)bq * EMBED + h * HDIM + lane] = acc;
}

// ---------------------------------------------------------------------------
extern "C" void kernel_launch(void* const* d_in, const int* in_sizes, int n_in,
                              void* d_out, int out_size)
{
    const float* query   = (const float*)d_in[0];
    const float* value   = (const float*)d_in[1];
    const float* qpos    = (const float*)d_in[2];
    const float* refpts  = (const float*)d_in[3];
    const float* W_val   = (const float*)d_in[4];
    const float* b_val   = (const float*)d_in[5];
    const float* W_off   = (const float*)d_in[6];
    const float* b_off   = (const float*)d_in[7];
    const float* W_attn  = (const float*)d_in[8];
    const float* b_attn  = (const float*)d_in[9];
    float* out = (float*)d_out;

    float *pv, *poff, *pattn;
    cudaGetSymbolAddress((void**)&pv, g_v);
    cudaGetSymbolAddress((void**)&poff, g_off);
    cudaGetSymbolAddress((void**)&pattn, g_attn);

    const int Mv = BS * NV;      // 39120
    const int Mq = BS * NQ;      // 20000

    // value projection -> permuted (b, h, pos, d) layout
    {
        dim3 grid(EMBED / GBN, (Mv + GBM - 1) / GBM);
        gemm2_kernel<<<grid, 256>>>(value, nullptr, W_val, b_val, pv,
                                    Mv, EMBED, EMBED, 1);
    }
    // offsets: g_off = (query + qpos) @ W_off + b_off
    {
        dim3 grid(256 / GBN, (Mq + GBM - 1) / GBM);
        gemm2_kernel<<<grid, 256>>>(query, qpos, W_off, b_off, poff,
                                    Mq, 256, EMBED, 0);
    }
    // attn logits: g_attn = (query + qpos) @ W_attn + b_attn
    {
        dim3 grid(128 / GBN, (Mq + GBM - 1) / GBM);
        gemm2_kernel<<<grid, 256>>>(query, qpos, W_attn, b_attn, pattn,
                                    Mq, 128, EMBED, 0);
    }
    // sampling + weighted sum
    {
        const int total_warps = BS * NQ * NHEAD;     // 160000
        const int warps_per_block = 8;
        const int blocks = (total_warps + warps_per_block - 1) / warps_per_block;
        sample_kernel<<<blocks, warps_per_block * 32>>>(refpts, out);
    }
}

// round 3
// speedup vs baseline: 1.1248x; 1.1139x over previous
#include <cuda_runtime.h>
#include <cuda_bf16.h>
#include <math.h>

#define BS 2
#define NQ 10000
#define NV 19560
#define EMBED 256
#define NHEAD 8
#define HDIM 32

typedef unsigned long long ull;

// Scratch (allocation-free rule: __device__ globals)
__device__ float g_v[(size_t)BS * NHEAD * NV * HDIM]; // (b, h, pos, d)
__device__ float g_off[(size_t)BS * NQ * 256];        // sampling offsets raw
__device__ float g_attn[(size_t)BS * NQ * 128];       // attn logits

// ---------------------------------------------------------------------------
// Packed-f32x2 GEMM: C[M,N] = (A + A2?) @ W[K,N] + bias[N]
// 128x128 tile, BK=16, 256 threads (16x16), 8x8 microtile per thread with the
// 8 columns split into two 4-wide strips (tx*4 and 64+tx*4) so B shared reads
// are at the 2-way LDS minimum. A is stored as duplicated (a,a) float2 pairs;
// with ty = tid>>4 a warp broadcasts A reads (conflict-free).
// Inner loop: 4 LDS.128 (A) + 2 LDS.128 (B) + 32 fma.rn.f32x2 per thread per k.
// ---------------------------------------------------------------------------
#define GBM 128
#define GBN 128
#define GBK 16

__device__ __forceinline__ void ffma2(ull& d, ull a, ull b) {
    asm("fma.rn.f32x2 %0, %1, %2, %0;" : "+l"(d) : "l"(a), "l"(b));
}

__global__ __launch_bounds__(256, 2)
void gemm2_kernel(const float* __restrict__ A,
                  const float* __restrict__ A2,
                  const float* __restrict__ W,
                  const float* __restrict__ bias,
                  float* __restrict__ C,
                  int M, int N, int K, int permuteV)
{
    __shared__ float2 As2[GBK][GBM];   // duplicated pairs (a,a), 16 KB
    __shared__ float  Bs[GBK][GBN];    // 8 KB

    const int tid = threadIdx.x;
    const int m0 = blockIdx.y * GBM;
    const int n0 = blockIdx.x * GBN;

    // global load mapping
    const int arow  = tid >> 1;          // 0..127
    const int acol  = (tid & 1) * 8;     // 0 or 8
    const int brow  = tid >> 4;          // 0..15
    const int bcol  = (tid & 15) * 8;    // 0..120

    // microtile mapping
    const int ty = tid >> 4;             // 0..15 : rows ty*8..+7
    const int tx = tid & 15;             // 0..15 : cols tx*4..+3 and 64+tx*4..+3

    ull acc[8][4];
#pragma unroll
    for (int i = 0; i < 8; i++)
#pragma unroll
        for (int j = 0; j < 4; j++) acc[i][j] = 0ull;

    for (int k0 = 0; k0 < K; k0 += GBK) {
        // ---- A tile: clamp row so OOB rows read valid memory (results unused)
        {
            int gm = m0 + arow;
            if (gm >= M) gm = M - 1;
            const float* ap = A + (size_t)gm * K + k0 + acol;
            float4 v0 = *(const float4*)(ap);
            float4 v1 = *(const float4*)(ap + 4);
            if (A2) {
                const float* a2p = A2 + (size_t)gm * K + k0 + acol;
                float4 u0 = *(const float4*)(a2p);
                float4 u1 = *(const float4*)(a2p + 4);
                v0.x += u0.x; v0.y += u0.y; v0.z += u0.z; v0.w += u0.w;
                v1.x += u1.x; v1.y += u1.y; v1.z += u1.z; v1.w += u1.w;
            }
            As2[acol + 0][arow] = make_float2(v0.x, v0.x);
            As2[acol + 1][arow] = make_float2(v0.y, v0.y);
            As2[acol + 2][arow] = make_float2(v0.z, v0.z);
            As2[acol + 3][arow] = make_float2(v0.w, v0.w);
            As2[acol + 4][arow] = make_float2(v1.x, v1.x);
            As2[acol + 5][arow] = make_float2(v1.y, v1.y);
            As2[acol + 6][arow] = make_float2(v1.z, v1.z);
            As2[acol + 7][arow] = make_float2(v1.w, v1.w);
        }
        // ---- B tile
        {
            const float* wp = W + (size_t)(k0 + brow) * N + n0 + bcol;
            *(float4*)&Bs[brow][bcol]     = *(const float4*)(wp);
            *(float4*)&Bs[brow][bcol + 4] = *(const float4*)(wp + 4);
        }
        __syncthreads();

#pragma unroll
        for (int k = 0; k < GBK; k++) {
            ull a[8], b[4];
            const ulonglong2* ap = (const ulonglong2*)&As2[k][ty * 8];
#pragma unroll
            for (int i = 0; i < 4; i++) {
                ulonglong2 t = ap[i];
                a[i * 2] = t.x; a[i * 2 + 1] = t.y;
            }
            {   // strip 0: cols tx*4..+3   (16B aligned, 256B warp span -> 2-way)
                ulonglong2 t = *(const ulonglong2*)&Bs[k][tx * 4];
                b[0] = t.x; b[1] = t.y;
            }
            {   // strip 1: cols 64+tx*4..+3
                ulonglong2 t = *(const ulonglong2*)&Bs[k][64 + tx * 4];
                b[2] = t.x; b[3] = t.y;
            }
#pragma unroll
            for (int i = 0; i < 8; i++)
#pragma unroll
                for (int j = 0; j < 4; j++)
                    ffma2(acc[i][j], a[i], b[j]);
        }
        __syncthreads();
    }

    // ---- epilogue: two 4-wide strips per row
    const int gn0 = n0 + tx * 4;
    const int gn1 = n0 + 64 + tx * 4;
    float4 bs0 = *(const float4*)(bias + gn0);
    float4 bs1 = *(const float4*)(bias + gn1);

#pragma unroll
    for (int i = 0; i < 8; i++) {
        const int gm = m0 + ty * 8 + i;
        if (gm >= M) break;
        float2 p0 = *(float2*)&acc[i][0];
        float2 p1 = *(float2*)&acc[i][1];
        float2 p2 = *(float2*)&acc[i][2];
        float2 p3 = *(float2*)&acc[i][3];
        float4 r0 = make_float4(p0.x + bs0.x, p0.y + bs0.y, p1.x + bs0.z, p1.y + bs0.w);
        float4 r1 = make_float4(p2.x + bs1.x, p2.y + bs1.y, p3.x + bs1.z, p3.y + bs1.w);

        if (permuteV) {
            const int b = gm / NV;
            const int pos = gm - b * NV;
            const int h0 = gn0 >> 5, d0 = gn0 & 31;
            const int h1 = gn1 >> 5, d1 = gn1 & 31;
            *(float4*)(C + (((size_t)(b * NHEAD + h0) * NV + pos) * HDIM + d0)) = r0;
            *(float4*)(C + (((size_t)(b * NHEAD + h1) * NV + pos) * HDIM + d1)) = r1;
        } else {
            *(float4*)(C + (size_t)gm * N + gn0) = r0;
            *(float4*)(C + (size_t)gm * N + gn1) = r1;
        }
    }
}

// ---------------------------------------------------------------------------
// Deformable sampling: one warp per (b, q, head); lane = channel d (HDIM==32).
// ---------------------------------------------------------------------------
__global__ void sample_kernel(const float* __restrict__ refpts,
                              float* __restrict__ out)
{
    const int gwarp = (blockIdx.x * blockDim.x + threadIdx.x) >> 5;
    const int lane = threadIdx.x & 31;
    const int total = BS * NQ * NHEAD;
    if (gwarp >= total) return;

    const int h  = gwarp & (NHEAD - 1);
    const int bq = gwarp >> 3;            // b*NQ + q
    const int b  = bq / NQ;

    const unsigned FULL = 0xFFFFFFFFu;

    // ---- softmax over 16 (level,point) slots ----
    float a = -INFINITY;
    if (lane < 16) a = g_attn[(size_t)bq * 128 + h * 16 + lane];
    float amax = a;
#pragma unroll
    for (int s = 16; s > 0; s >>= 1)
        amax = fmaxf(amax, __shfl_xor_sync(FULL, amax, s));
    float e = (lane < 16) ? __expf(a - amax) : 0.f;
    float esum = e;
#pragma unroll
    for (int s = 16; s > 0; s >>= 1)
        esum += __shfl_xor_sync(FULL, esum, s);
    const float wgt = e / esum;

    // ---- per-slot pixel coordinates (lanes 0..15) ----
    const float LW[4] = {160.f, 80.f, 40.f, 20.f};
    const float LH[4] = {92.f, 46.f, 23.f, 12.f};

    float x = 0.f, y = 0.f;
    if (lane < 16) {
        const int l  = lane >> 2;
        const int pt = lane & 3;
        const float offx = g_off[(size_t)bq * 256 + h * 32 + l * 8 + pt * 2 + 0];
        const float offy = g_off[(size_t)bq * 256 + h * 32 + l * 8 + pt * 2 + 1];
        const float rx = refpts[(size_t)bq * 8 + pt * 2 + 0];
        const float ry = refpts[(size_t)bq * 8 + pt * 2 + 1];
        const float locx = rx + offx / LW[l];
        const float locy = ry + offy / LH[l];
        x = fmaf(locx, LW[l], -0.5f);
        y = fmaf(locy, LH[l], -0.5f);
    }

    const int HH[4] = {92, 46, 23, 12};
    const int WW[4] = {160, 80, 40, 20};
    const int ST[4] = {0, 14720, 18400, 19320};

    const float* __restrict__ vp =
        g_v + ((size_t)(b * NHEAD + h) * NV) * HDIM + lane;

    float acc = 0.f;

#pragma unroll
    for (int p = 0; p < 16; p++) {
        const float xp = __shfl_sync(FULL, x, p);
        const float yp = __shfl_sync(FULL, y, p);
        const float wp = __shfl_sync(FULL, wgt, p);
        const int l = p >> 2;
        const int Hl = HH[l], Wl = WW[l], base = ST[l];

        const float x0f = floorf(xp), y0f = floorf(yp);
        const float wx1 = xp - x0f;
        const float wy1r = yp - y0f;
        const float wx0 = 1.f - wx1;
        const float wy1 = wy1r * wp;          // fold softmax weight in
        const float wy0 = (1.f - wy1r) * wp;
        const int x0 = (int)x0f, y0 = (int)y0f;

        const int idx00 = (base + y0 * Wl + x0) * HDIM;
        const bool vx0 = (unsigned)x0 < (unsigned)Wl;
        const bool vx1 = (unsigned)(x0 + 1) < (unsigned)Wl;
        const bool vy0 = (unsigned)y0 < (unsigned)Hl;
        const bool vy1 = (unsigned)(y0 + 1) < (unsigned)Hl;
        const int rstep = Wl * HDIM;

        if (vy0 & vx0) acc = fmaf(__ldg(vp + idx00),                wy0 * wx0, acc);
        if (vy0 & vx1) acc = fmaf(__ldg(vp + idx00 + HDIM),         wy0 * wx1, acc);
        if (vy1 & vx0) acc = fmaf(__ldg(vp + idx00 + rstep),        wy1 * wx0, acc);
        if (vy1 & vx1) acc = fmaf(__ldg(vp + idx00 + rstep + HDIM), wy1 * wx1, acc);
    }

    out[(size_t)bq * EMBED + h * HDIM + lane] = acc;
}

// ---------------------------------------------------------------------------
extern "C" void kernel_launch(void* const* d_in, const int* in_sizes, int n_in,
                              void* d_out, int out_size)
{
    const float* query   = (const float*)d_in[0];
    const float* value   = (const float*)d_in[1];
    const float* qpos    = (const float*)d_in[2];
    const float* refpts  = (const float*)d_in[3];
    const float* W_val   = (const float*)d_in[4];
    const float* b_val   = (const float*)d_in[5];
    const float* W_off   = (const float*)d_in[6];
    const float* b_off   = (const float*)d_in[7];
    const float* W_attn  = (const float*)d_in[8];
    const float* b_attn  = (const float*)d_in[9];
    float* out = (float*)d_out;

    float *pv, *poff, *pattn;
    cudaGetSymbolAddress((void**)&pv, g_v);
    cudaGetSymbolAddress((void**)&poff, g_off);
    cudaGetSymbolAddress((void**)&pattn, g_attn);

    const int Mv = BS * NV;      // 39120
    const int Mq = BS * NQ;      // 20000

    // value projection -> permuted (b, h, pos, d) layout
    {
        dim3 grid(EMBED / GBN, (Mv + GBM - 1) / GBM);
        gemm2_kernel<<<grid, 256>>>(value, nullptr, W_val, b_val, pv,
                                    Mv, EMBED, EMBED, 1);
    }
    // offsets: g_off = (query + qpos) @ W_off + b_off
    {
        dim3 grid(256 / GBN, (Mq + GBM - 1) / GBM);
        gemm2_kernel<<<grid, 256>>>(query, qpos, W_off, b_off, poff,
                                    Mq, 256, EMBED, 0);
    }
    // attn logits: g_attn = (query + qpos) @ W_attn + b_attn
    {
        dim3 grid(128 / GBN, (Mq + GBM - 1) / GBM);
        gemm2_kernel<<<grid, 256>>>(query, qpos, W_attn, b_attn, pattn,
                                    Mq, 128, EMBED, 0);
    }
    // sampling + weighted sum
    {
        const int total_warps = BS * NQ * NHEAD;     // 160000
        const int warps_per_block = 8;
        const int blocks = (total_warps + warps_per_block - 1) / warps_per_block;
        sample_kernel<<<blocks, warps_per_block * 32>>>(refpts, out);
    }
}

// round 5
// speedup vs baseline: 1.3845x; 1.2309x over previous
#include <cuda_runtime.h>
#include <cuda_bf16.h>
#include <math.h>
#include <stdint.h>

#define BS 2
#define NQ 10000
#define NV 19560
#define EMBED 256
#define NHEAD 8
#define HDIM 32

// Scratch (allocation-free rule: __device__ globals)
__device__ float g_v[(size_t)BS * NHEAD * NV * HDIM]; // (b, h, pos, d)
__device__ float g_off[(size_t)BS * NQ * 256];        // sampling offsets raw
__device__ float g_attn[(size_t)BS * NQ * 128];       // attn logits

// ===========================================================================
// bf16 2-term-split tensor-core GEMM via mma.sync (valid on plain sm_103):
//   C[M,N] = (A + A2?) @ W[K=256, N] + bias,  C ≈ Ah·Bh + Ah·Bl + Al·Bh
// Block 128x128, 8 warps (2m x 4n), warp tile 64x32, BK=16.
// SMEM: A [m][k] and B-transposed [n][k], bf16, stride 18 (pad) -> no conflicts.
// ===========================================================================
#define TCK 256
#define TBK 16
#define SSTR 18   // padded bf16 stride

__device__ __forceinline__ void mma_bf16(float& c0, float& c1, float& c2, float& c3,
                                         uint32_t a0, uint32_t a1, uint32_t a2, uint32_t a3,
                                         uint32_t b0, uint32_t b1) {
    asm volatile(
        "mma.sync.aligned.m16n8k16.row.col.f32.bf16.bf16.f32 "
        "{%0,%1,%2,%3}, {%4,%5,%6,%7}, {%8,%9}, {%0,%1,%2,%3};"
        : "+f"(c0), "+f"(c1), "+f"(c2), "+f"(c3)
        : "r"(a0), "r"(a1), "r"(a2), "r"(a3), "r"(b0), "r"(b1));
}

__device__ __forceinline__ void cvt_hl(float x, __nv_bfloat16& h, __nv_bfloat16& l) {
    h = __float2bfloat16_rn(x);
    l = __float2bfloat16_rn(x - __bfloat162float(h));
}

__global__ __launch_bounds__(256)
void mma_gemm(const float* __restrict__ A, const float* __restrict__ A2,
              const float* __restrict__ W, const float* __restrict__ bias,
              float* __restrict__ C, int M, int N, int permuteV)
{
    __shared__ __nv_bfloat16 Ah[128 * SSTR];
    __shared__ __nv_bfloat16 Al[128 * SSTR];
    __shared__ __nv_bfloat16 Bh[128 * SSTR];
    __shared__ __nv_bfloat16 Bl[128 * SSTR];

    const int tid = threadIdx.x;
    const int wid = tid >> 5;
    const int lane = tid & 31;
    const int m0 = blockIdx.y * 128;
    const int n0 = blockIdx.x * 128;

    const int wm = wid >> 2;         // 0..1  -> rows wm*64
    const int wn = wid & 3;          // 0..3  -> cols wn*32
    const int grp = lane >> 2;       // 0..7
    const int qid = lane & 3;        // 0..3

    float acc[4][4][4];              // [m-tile][n-tile][c0..c3]
#pragma unroll
    for (int i = 0; i < 4; i++)
#pragma unroll
        for (int j = 0; j < 4; j++)
#pragma unroll
            for (int r = 0; r < 4; r++) acc[i][j][r] = 0.f;

    for (int k0 = 0; k0 < TCK; k0 += TBK) {
        // ---- A tile: 128 rows x 16 k  (thread: row = tid>>1, kb = (tid&1)*8)
        {
            const int row = tid >> 1;
            const int kb = (tid & 1) * 8;
            int gm = m0 + row;
            if (gm >= M) gm = M - 1;
            const float* ap = A + (size_t)gm * TCK + k0 + kb;
            float4 v0 = *(const float4*)(ap);
            float4 v1 = *(const float4*)(ap + 4);
            if (A2) {
                const float* a2p = A2 + (size_t)gm * TCK + k0 + kb;
                float4 u0 = *(const float4*)(a2p);
                float4 u1 = *(const float4*)(a2p + 4);
                v0.x += u0.x; v0.y += u0.y; v0.z += u0.z; v0.w += u0.w;
                v1.x += u1.x; v1.y += u1.y; v1.z += u1.z; v1.w += u1.w;
            }
            float f[8] = {v0.x, v0.y, v0.z, v0.w, v1.x, v1.y, v1.z, v1.w};
            __nv_bfloat16* ah = Ah + row * SSTR + kb;
            __nv_bfloat16* al = Al + row * SSTR + kb;
#pragma unroll
            for (int j = 0; j < 8; j++) {
                __nv_bfloat16 h, l;
                cvt_hl(f[j], h, l);
                ah[j] = h; al[j] = l;
            }
        }
        // ---- B tile (transpose): Bs[n][k] = W[k0+k][n0+n]
        {
            const int k = tid >> 4;          // 0..15
            const int nb = (tid & 15) * 8;   // 0..120
            const float* wp = W + (size_t)(k0 + k) * N + n0 + nb;
            float4 v0 = *(const float4*)(wp);
            float4 v1 = *(const float4*)(wp + 4);
            float f[8] = {v0.x, v0.y, v0.z, v0.w, v1.x, v1.y, v1.z, v1.w};
#pragma unroll
            for (int j = 0; j < 8; j++) {
                __nv_bfloat16 h, l;
                cvt_hl(f[j], h, l);
                Bh[(nb + j) * SSTR + k] = h;
                Bl[(nb + j) * SSTR + k] = l;
            }
        }
        __syncthreads();

        // ---- fragments
        uint32_t ah[4][4], al[4][4], bh[4][2], bl[4][2];
#pragma unroll
        for (int tm = 0; tm < 4; tm++) {
            const int r0 = wm * 64 + tm * 16 + grp;
            const int cc = qid * 2;
            ah[tm][0] = *(const uint32_t*)&Ah[(r0)     * SSTR + cc];
            ah[tm][1] = *(const uint32_t*)&Ah[(r0 + 8) * SSTR + cc];
            ah[tm][2] = *(const uint32_t*)&Ah[(r0)     * SSTR + cc + 8];
            ah[tm][3] = *(const uint32_t*)&Ah[(r0 + 8) * SSTR + cc + 8];
            al[tm][0] = *(const uint32_t*)&Al[(r0)     * SSTR + cc];
            al[tm][1] = *(const uint32_t*)&Al[(r0 + 8) * SSTR + cc];
            al[tm][2] = *(const uint32_t*)&Al[(r0)     * SSTR + cc + 8];
            al[tm][3] = *(const uint32_t*)&Al[(r0 + 8) * SSTR + cc + 8];
        }
#pragma unroll
        for (int tn = 0; tn < 4; tn++) {
            const int n = wn * 32 + tn * 8 + grp;
            const int cc = qid * 2;
            bh[tn][0] = *(const uint32_t*)&Bh[n * SSTR + cc];
            bh[tn][1] = *(const uint32_t*)&Bh[n * SSTR + cc + 8];
            bl[tn][0] = *(const uint32_t*)&Bl[n * SSTR + cc];
            bl[tn][1] = *(const uint32_t*)&Bl[n * SSTR + cc + 8];
        }

#pragma unroll
        for (int tm = 0; tm < 4; tm++)
#pragma unroll
            for (int tn = 0; tn < 4; tn++) {
                float* c = acc[tm][tn];
                mma_bf16(c[0], c[1], c[2], c[3],
                         ah[tm][0], ah[tm][1], ah[tm][2], ah[tm][3],
                         bh[tn][0], bh[tn][1]);
                mma_bf16(c[0], c[1], c[2], c[3],
                         ah[tm][0], ah[tm][1], ah[tm][2], ah[tm][3],
                         bl[tn][0], bl[tn][1]);
                mma_bf16(c[0], c[1], c[2], c[3],
                         al[tm][0], al[tm][1], al[tm][2], al[tm][3],
                         bh[tn][0], bh[tn][1]);
            }
        __syncthreads();
    }

    // ---- epilogue: c0,c1 at (row grp, cols 2q..2q+1), c2,c3 at row grp+8
#pragma unroll
    for (int tm = 0; tm < 4; tm++) {
#pragma unroll
        for (int half = 0; half < 2; half++) {
            const int gm = m0 + wm * 64 + tm * 16 + grp + half * 8;
            if (gm >= M) continue;
#pragma unroll
            for (int tn = 0; tn < 4; tn++) {
                const int gn = n0 + wn * 32 + tn * 8 + qid * 2;
                float2 bsv = *(const float2*)(bias + gn);
                float2 o;
                o.x = acc[tm][tn][half * 2 + 0] + bsv.x;
                o.y = acc[tm][tn][half * 2 + 1] + bsv.y;
                if (permuteV) {
                    const int b = gm / NV;
                    const int pos = gm - b * NV;
                    const int h = gn >> 5, d = gn & 31;
                    *(float2*)(C + (((size_t)(b * NHEAD + h) * NV + pos) * HDIM + d)) = o;
                } else {
                    *(float2*)(C + (size_t)gm * N + gn) = o;
                }
            }
        }
    }
}

// ---------------------------------------------------------------------------
// Deformable sampling (unchanged): one warp per (b, q, head).
// ---------------------------------------------------------------------------
__global__ void sample_kernel(const float* __restrict__ refpts,
                              float* __restrict__ out)
{
    const int gwarp = (blockIdx.x * blockDim.x + threadIdx.x) >> 5;
    const int lane = threadIdx.x & 31;
    const int total = BS * NQ * NHEAD;
    if (gwarp >= total) return;

    const int h  = gwarp & (NHEAD - 1);
    const int bq = gwarp >> 3;
    const int b  = bq / NQ;

    const unsigned FULL = 0xFFFFFFFFu;

    float a = -INFINITY;
    if (lane < 16) a = g_attn[(size_t)bq * 128 + h * 16 + lane];
    float amax = a;
#pragma unroll
    for (int s = 16; s > 0; s >>= 1)
        amax = fmaxf(amax, __shfl_xor_sync(FULL, amax, s));
    float e = (lane < 16) ? __expf(a - amax) : 0.f;
    float esum = e;
#pragma unroll
    for (int s = 16; s > 0; s >>= 1)
        esum += __shfl_xor_sync(FULL, esum, s);
    const float wgt = e / esum;

    const float LW[4] = {160.f, 80.f, 40.f, 20.f};
    const float LH[4] = {92.f, 46.f, 23.f, 12.f};

    float x = 0.f, y = 0.f;
    if (lane < 16) {
        const int l  = lane >> 2;
        const int pt = lane & 3;
        const float offx = g_off[(size_t)bq * 256 + h * 32 + l * 8 + pt * 2 + 0];
        const float offy = g_off[(size_t)bq * 256 + h * 32 + l * 8 + pt * 2 + 1];
        const float rx = refpts[(size_t)bq * 8 + pt * 2 + 0];
        const float ry = refpts[(size_t)bq * 8 + pt * 2 + 1];
        const float locx = rx + offx / LW[l];
        const float locy = ry + offy / LH[l];
        x = fmaf(locx, LW[l], -0.5f);
        y = fmaf(locy, LH[l], -0.5f);
    }

    const int HH[4] = {92, 46, 23, 12};
    const int WW[4] = {160, 80, 40, 20};
    const int ST[4] = {0, 14720, 18400, 19320};

    const float* __restrict__ vp =
        g_v + ((size_t)(b * NHEAD + h) * NV) * HDIM + lane;

    float acc = 0.f;

#pragma unroll
    for (int p = 0; p < 16; p++) {
        const float xp = __shfl_sync(FULL, x, p);
        const float yp = __shfl_sync(FULL, y, p);
        const float wp = __shfl_sync(FULL, wgt, p);
        const int l = p >> 2;
        const int Hl = HH[l], Wl = WW[l], base = ST[l];

        const float x0f = floorf(xp), y0f = floorf(yp);
        const float wx1 = xp - x0f;
        const float wy1r = yp - y0f;
        const float wx0 = 1.f - wx1;
        const float wy1 = wy1r * wp;
        const float wy0 = (1.f - wy1r) * wp;
        const int x0 = (int)x0f, y0 = (int)y0f;

        const int idx00 = (base + y0 * Wl + x0) * HDIM;
        const bool vx0 = (unsigned)x0 < (unsigned)Wl;
        const bool vx1 = (unsigned)(x0 + 1) < (unsigned)Wl;
        const bool vy0 = (unsigned)y0 < (unsigned)Hl;
        const bool vy1 = (unsigned)(y0 + 1) < (unsigned)Hl;
        const int rstep = Wl * HDIM;

        if (vy0 & vx0) acc = fmaf(__ldg(vp + idx00),                wy0 * wx0, acc);
        if (vy0 & vx1) acc = fmaf(__ldg(vp + idx00 + HDIM),         wy0 * wx1, acc);
        if (vy1 & vx0) acc = fmaf(__ldg(vp + idx00 + rstep),        wy1 * wx0, acc);
        if (vy1 & vx1) acc = fmaf(__ldg(vp + idx00 + rstep + HDIM), wy1 * wx1, acc);
    }

    out[(size_t)bq * EMBED + h * HDIM + lane] = acc;
}

// ---------------------------------------------------------------------------
extern "C" void kernel_launch(void* const* d_in, const int* in_sizes, int n_in,
                              void* d_out, int out_size)
{
    const float* query   = (const float*)d_in[0];
    const float* value   = (const float*)d_in[1];
    const float* qpos    = (const float*)d_in[2];
    const float* refpts  = (const float*)d_in[3];
    const float* W_val   = (const float*)d_in[4];
    const float* b_val   = (const float*)d_in[5];
    const float* W_off   = (const float*)d_in[6];
    const float* b_off   = (const float*)d_in[7];
    const float* W_attn  = (const float*)d_in[8];
    const float* b_attn  = (const float*)d_in[9];
    float* out = (float*)d_out;

    float *pv, *poff, *pattn;
    cudaGetSymbolAddress((void**)&pv, g_v);
    cudaGetSymbolAddress((void**)&poff, g_off);
    cudaGetSymbolAddress((void**)&pattn, g_attn);

    const int Mv = BS * NV;      // 39120
    const int Mq = BS * NQ;      // 20000

    // value projection -> permuted (b, h, pos, d) layout
    mma_gemm<<<dim3(2, (Mv + 127) / 128), 256>>>(
        value, nullptr, W_val, b_val, pv, Mv, 256, 1);
    // offsets: g_off = (query + qpos) @ W_off + b_off
    mma_gemm<<<dim3(2, (Mq + 127) / 128), 256>>>(
        query, qpos, W_off, b_off, poff, Mq, 256, 0);
    // attn logits: g_attn = (query + qpos) @ W_attn + b_attn
    mma_gemm<<<dim3(1, (Mq + 127) / 128), 256>>>(
        query, qpos, W_attn, b_attn, pattn, Mq, 128, 0);

    // sampling + weighted sum
    {
        const int total_warps = BS * NQ * NHEAD;
        const int warps_per_block = 8;
        const int blocks = (total_warps + warps_per_block - 1) / warps_per_block;
        sample_kernel<<<blocks, warps_per_block * 32>>>(refpts, out);
    }
}

// round 6
// speedup vs baseline: 1.7964x; 1.2975x over previous
#include <cuda_runtime.h>
#include <cuda_bf16.h>
#include <math.h>
#include <stdint.h>

#define BS 2
#define NQ 10000
#define NV 19560
#define EMBED 256
#define NHEAD 8
#define HDIM 32

typedef __nv_bfloat16 bf16;

// Scratch (allocation-free rule: __device__ globals)
__device__ float g_v[(size_t)BS * NHEAD * NV * HDIM]; // (b, h, pos, d)
__device__ float g_off[(size_t)BS * NQ * 256];
__device__ float g_attn[(size_t)BS * NQ * 128];

// bf16 hi/lo split operands (precomputed once per call)
__device__ bf16 g_qh[(size_t)BS * NQ * 256];
__device__ bf16 g_ql[(size_t)BS * NQ * 256];
__device__ bf16 g_vh[(size_t)BS * NV * 256];
__device__ bf16 g_vl[(size_t)BS * NV * 256];
__device__ bf16 g_wvh[256 * 256], g_wvl[256 * 256];   // W_val^T  [n][k]
__device__ bf16 g_woh[256 * 256], g_wol[256 * 256];   // W_off^T  [n][k]
__device__ bf16 g_wah[128 * 256], g_wal[128 * 256];   // W_attn^T [n][k]

// ===========================================================================
// helpers
// ===========================================================================
__device__ __forceinline__ uint32_t smem_u32(const void* p) {
    uint32_t a;
    asm("{ .reg .u64 t; cvta.to.shared.u64 t, %1; cvt.u32.u64 %0, t; }"
        : "=r"(a) : "l"(p));
    return a;
}
__device__ __forceinline__ void cvt_hl(float x, bf16& h, bf16& l) {
    h = __float2bfloat16_rn(x);
    l = __float2bfloat16_rn(x - __bfloat162float(h));
}

#define CP16(dst, src) \
    asm volatile("cp.async.cg.shared.global [%0], [%1], 16;" \
                 :: "r"(dst), "l"(src))
#define CP_COMMIT() asm volatile("cp.async.commit_group;")
#define CP_WAIT(n)  asm volatile("cp.async.wait_group %0;" :: "n"(n))

#define LDSM_X4(r0, r1, r2, r3, addr) \
    asm volatile("ldmatrix.sync.aligned.m8n8.x4.shared.b16 {%0,%1,%2,%3}, [%4];" \
                 : "=r"(r0), "=r"(r1), "=r"(r2), "=r"(r3) : "r"(addr))

__device__ __forceinline__ void mma_bf16(float* c,
                                         uint32_t a0, uint32_t a1, uint32_t a2, uint32_t a3,
                                         uint32_t b0, uint32_t b1) {
    asm volatile(
        "mma.sync.aligned.m16n8k16.row.col.f32.bf16.bf16.f32 "
        "{%0,%1,%2,%3}, {%4,%5,%6,%7}, {%8,%9}, {%0,%1,%2,%3};"
        : "+f"(c[0]), "+f"(c[1]), "+f"(c[2]), "+f"(c[3])
        : "r"(a0), "r"(a1), "r"(a2), "r"(a3), "r"(b0), "r"(b1));
}

// ===========================================================================
// conversion kernels
// ===========================================================================
__global__ void conv_pair(const float* __restrict__ x, const float* __restrict__ x2,
                          bf16* __restrict__ hi, bf16* __restrict__ lo, int n4)
{
    const int i = blockIdx.x * blockDim.x + threadIdx.x;
    if (i >= n4) return;
    float4 v = ((const float4*)x)[i];
    if (x2) {
        float4 u = ((const float4*)x2)[i];
        v.x += u.x; v.y += u.y; v.z += u.z; v.w += u.w;
    }
    bf16 h[4], l[4];
    cvt_hl(v.x, h[0], l[0]); cvt_hl(v.y, h[1], l[1]);
    cvt_hl(v.z, h[2], l[2]); cvt_hl(v.w, h[3], l[3]);
    ((uint2*)hi)[i] = *(uint2*)h;
    ((uint2*)lo)[i] = *(uint2*)l;
}

// W [256][N] -> out [N][256] hi/lo (32x32 smem tile transpose)
__global__ void conv_w_t(const float* __restrict__ W,
                         bf16* __restrict__ th, bf16* __restrict__ tl, int N)
{
    __shared__ float t[32][33];
    const int k0 = blockIdx.y * 32, n0 = blockIdx.x * 32;
    const int tx = threadIdx.x & 31, ty = threadIdx.x >> 5;  // 32 x 8
#pragma unroll
    for (int j = 0; j < 4; j++)
        t[ty + j * 8][tx] = W[(size_t)(k0 + ty + j * 8) * N + n0 + tx];
    __syncthreads();
#pragma unroll
    for (int j = 0; j < 4; j++) {
        const int n = n0 + ty + j * 8;
        const int k = k0 + tx;
        bf16 h, l;
        cvt_hl(t[tx][ty + j * 8], h, l);
        th[(size_t)n * 256 + k] = h;
        tl[(size_t)n * 256 + k] = l;
    }
}

// ===========================================================================
// bf16 3-term mma.sync GEMM with cp.async double buffering + ldmatrix.
// C[M,N] = Ah@Bh^T + Ah@Bl^T + Al@Bh^T + bias.  A [m][k], B [n][k], K=256.
// Block 128x128, 8 warps (2m x 4n), warp tile 64x32, BK=32 chunks.
// ===========================================================================
#define TSTR 40                       // padded bf16 row stride (80 B)
#define TILE_B (128 * TSTR * 2)       // 10240 B per tile
#define BUF_B  (4 * TILE_B)           // Ah, Al, Bh, Bl
#define SMEM_TOT (2 * BUF_B)          // 81920 B

__device__ __forceinline__ void load_chunk(uint32_t sb,
                                           const bf16* __restrict__ Ah_g,
                                           const bf16* __restrict__ Al_g,
                                           const bf16* __restrict__ Bh_g,
                                           const bf16* __restrict__ Bl_g,
                                           int m0, int n0, int M, int k0, int tid)
{
#pragma unroll
    for (int i = 0; i < 2; i++) {
        const int cid = tid + i * 256;
        const int row = cid >> 2;
        const int cp = cid & 3;
        int gm = m0 + row;
        if (gm >= M) gm = M - 1;
        const uint32_t doff = (uint32_t)(row * 80 + cp * 16);
        const size_t asrc = (size_t)gm * 256 + k0 + cp * 8;
        const size_t bsrc = (size_t)(n0 + row) * 256 + k0 + cp * 8;
        CP16(sb + doff,              Ah_g + asrc);
        CP16(sb + TILE_B + doff,     Al_g + asrc);
        CP16(sb + 2 * TILE_B + doff, Bh_g + bsrc);
        CP16(sb + 3 * TILE_B + doff, Bl_g + bsrc);
    }
}

__global__ __launch_bounds__(256)
void mma_gemm2(const bf16* __restrict__ Ah_g, const bf16* __restrict__ Al_g,
               const bf16* __restrict__ Bh_g, const bf16* __restrict__ Bl_g,
               const float* __restrict__ bias, float* __restrict__ C,
               int M, int N, int permuteV)
{
    extern __shared__ char smem[];
    const uint32_t sbase = smem_u32(smem);
    const int tid = threadIdx.x;
    const int wid = tid >> 5;
    const int lane = tid & 31;
    const int m0 = blockIdx.y * 128;
    const int n0 = blockIdx.x * 128;

    const int wm = wid >> 2;
    const int wn = wid & 3;
    const int grp = lane >> 2;
    const int qid = lane & 3;

    float acc[4][4][4];
#pragma unroll
    for (int i = 0; i < 4; i++)
#pragma unroll
        for (int j = 0; j < 4; j++)
#pragma unroll
            for (int r = 0; r < 4; r++) acc[i][j][r] = 0.f;

    // ldmatrix lane addressing
    const int mat = lane >> 3;
    const int arow_off = (lane & 7) + (mat & 1) * 8;        // A: mats 1,3 -> +8 rows
    const int akoff = (mat >> 1) * 16;                       // A: mats 2,3 -> +8 bf16
    const int brow_off = (lane & 7) + ((mat >> 1) & 1) * 8;  // B: mats 2,3 -> +8 n
    const int bkoff = (mat & 1) * 16;                        // B: mats 1,3 -> +8 k

    load_chunk(sbase, Ah_g, Al_g, Bh_g, Bl_g, m0, n0, M, 0, tid);
    CP_COMMIT();

    const int NCH = 256 / 32;
#pragma unroll 1
    for (int c = 0; c < NCH; c++) {
        if (c + 1 < NCH) {
            load_chunk(sbase + ((c + 1) & 1) * BUF_B,
                       Ah_g, Al_g, Bh_g, Bl_g, m0, n0, M, (c + 1) * 32, tid);
            CP_COMMIT();
            CP_WAIT(1);
        } else {
            CP_WAIT(0);
        }
        __syncthreads();

        const uint32_t sA = sbase + (c & 1) * BUF_B;
        const uint32_t sAl = sA + TILE_B;
        const uint32_t sBh = sA + 2 * TILE_B;
        const uint32_t sBl = sA + 3 * TILE_B;

#pragma unroll
        for (int ks = 0; ks < 2; ks++) {
            const int kb = ks * 32;  // byte offset of k-step within row
            uint32_t ah[4][4], al[4][4], bh[4][2], bl[4][2];
#pragma unroll
            for (int tm = 0; tm < 4; tm++) {
                const uint32_t aaddr =
                    (uint32_t)((wm * 64 + tm * 16 + arow_off) * 80 + kb + akoff);
                LDSM_X4(ah[tm][0], ah[tm][1], ah[tm][2], ah[tm][3], sA + aaddr);
                LDSM_X4(al[tm][0], al[tm][1], al[tm][2], al[tm][3], sAl + aaddr);
            }
#pragma unroll
            for (int half = 0; half < 2; half++) {
                const uint32_t baddr =
                    (uint32_t)((wn * 32 + half * 16 + brow_off) * 80 + kb + bkoff);
                uint32_t t0, t1, t2, t3;
                LDSM_X4(t0, t1, t2, t3, sBh + baddr);
                bh[half * 2][0] = t0; bh[half * 2][1] = t1;
                bh[half * 2 + 1][0] = t2; bh[half * 2 + 1][1] = t3;
                LDSM_X4(t0, t1, t2, t3, sBl + baddr);
                bl[half * 2][0] = t0; bl[half * 2][1] = t1;
                bl[half * 2 + 1][0] = t2; bl[half * 2 + 1][1] = t3;
            }
#pragma unroll
            for (int tm = 0; tm < 4; tm++)
#pragma unroll
                for (int tn = 0; tn < 4; tn++) {
                    float* cc = acc[tm][tn];
                    mma_bf16(cc, ah[tm][0], ah[tm][1], ah[tm][2], ah[tm][3],
                             bh[tn][0], bh[tn][1]);
                    mma_bf16(cc, ah[tm][0], ah[tm][1], ah[tm][2], ah[tm][3],
                             bl[tn][0], bl[tn][1]);
                    mma_bf16(cc, al[tm][0], al[tm][1], al[tm][2], al[tm][3],
                             bh[tn][0], bh[tn][1]);
                }
        }
        __syncthreads();
    }

    // epilogue
#pragma unroll
    for (int tm = 0; tm < 4; tm++) {
#pragma unroll
        for (int half = 0; half < 2; half++) {
            const int gm = m0 + wm * 64 + tm * 16 + grp + half * 8;
            if (gm >= M) continue;
#pragma unroll
            for (int tn = 0; tn < 4; tn++) {
                const int gn = n0 + wn * 32 + tn * 8 + qid * 2;
                float2 bsv = *(const float2*)(bias + gn);
                float2 o;
                o.x = acc[tm][tn][half * 2 + 0] + bsv.x;
                o.y = acc[tm][tn][half * 2 + 1] + bsv.y;
                if (permuteV) {
                    const int b = gm / NV;
                    const int pos = gm - b * NV;
                    const int h = gn >> 5, d = gn & 31;
                    *(float2*)(C + (((size_t)(b * NHEAD + h) * NV + pos) * HDIM + d)) = o;
                } else {
                    *(float2*)(C + (size_t)gm * N + gn) = o;
                }
            }
        }
    }
}

// ---------------------------------------------------------------------------
// Deformable sampling (unchanged): one warp per (b, q, head).
// ---------------------------------------------------------------------------
__global__ void sample_kernel(const float* __restrict__ refpts,
                              float* __restrict__ out)
{
    const int gwarp = (blockIdx.x * blockDim.x + threadIdx.x) >> 5;
    const int lane = threadIdx.x & 31;
    const int total = BS * NQ * NHEAD;
    if (gwarp >= total) return;

    const int h  = gwarp & (NHEAD - 1);
    const int bq = gwarp >> 3;
    const int b  = bq / NQ;

    const unsigned FULL = 0xFFFFFFFFu;

    float a = -INFINITY;
    if (lane < 16) a = g_attn[(size_t)bq * 128 + h * 16 + lane];
    float amax = a;
#pragma unroll
    for (int s = 16; s > 0; s >>= 1)
        amax = fmaxf(amax, __shfl_xor_sync(FULL, amax, s));
    float e = (lane < 16) ? __expf(a - amax) : 0.f;
    float esum = e;
#pragma unroll
    for (int s = 16; s > 0; s >>= 1)
        esum += __shfl_xor_sync(FULL, esum, s);
    const float wgt = e / esum;

    const float LW[4] = {160.f, 80.f, 40.f, 20.f};
    const float LH[4] = {92.f, 46.f, 23.f, 12.f};

    float x = 0.f, y = 0.f;
    if (lane < 16) {
        const int l  = lane >> 2;
        const int pt = lane & 3;
        const float offx = g_off[(size_t)bq * 256 + h * 32 + l * 8 + pt * 2 + 0];
        const float offy = g_off[(size_t)bq * 256 + h * 32 + l * 8 + pt * 2 + 1];
        const float rx = refpts[(size_t)bq * 8 + pt * 2 + 0];
        const float ry = refpts[(size_t)bq * 8 + pt * 2 + 1];
        const float locx = rx + offx / LW[l];
        const float locy = ry + offy / LH[l];
        x = fmaf(locx, LW[l], -0.5f);
        y = fmaf(locy, LH[l], -0.5f);
    }

    const int HH[4] = {92, 46, 23, 12};
    const int WW[4] = {160, 80, 40, 20};
    const int ST[4] = {0, 14720, 18400, 19320};

    const float* __restrict__ vp =
        g_v + ((size_t)(b * NHEAD + h) * NV) * HDIM + lane;

    float acc = 0.f;

#pragma unroll
    for (int p = 0; p < 16; p++) {
        const float xp = __shfl_sync(FULL, x, p);
        const float yp = __shfl_sync(FULL, y, p);
        const float wp = __shfl_sync(FULL, wgt, p);
        const int l = p >> 2;
        const int Hl = HH[l], Wl = WW[l], base = ST[l];

        const float x0f = floorf(xp), y0f = floorf(yp);
        const float wx1 = xp - x0f;
        const float wy1r = yp - y0f;
        const float wx0 = 1.f - wx1;
        const float wy1 = wy1r * wp;
        const float wy0 = (1.f - wy1r) * wp;
        const int x0 = (int)x0f, y0 = (int)y0f;

        const int idx00 = (base + y0 * Wl + x0) * HDIM;
        const bool vx0 = (unsigned)x0 < (unsigned)Wl;
        const bool vx1 = (unsigned)(x0 + 1) < (unsigned)Wl;
        const bool vy0 = (unsigned)y0 < (unsigned)Hl;
        const bool vy1 = (unsigned)(y0 + 1) < (unsigned)Hl;
        const int rstep = Wl * HDIM;

        if (vy0 & vx0) acc = fmaf(__ldg(vp + idx00),                wy0 * wx0, acc);
        if (vy0 & vx1) acc = fmaf(__ldg(vp + idx00 + HDIM),         wy0 * wx1, acc);
        if (vy1 & vx0) acc = fmaf(__ldg(vp + idx00 + rstep),        wy1 * wx0, acc);
        if (vy1 & vx1) acc = fmaf(__ldg(vp + idx00 + rstep + HDIM), wy1 * wx1, acc);
    }

    out[(size_t)bq * EMBED + h * HDIM + lane] = acc;
}

// ---------------------------------------------------------------------------
extern "C" void kernel_launch(void* const* d_in, const int* in_sizes, int n_in,
                              void* d_out, int out_size)
{
    const float* query   = (const float*)d_in[0];
    const float* value   = (const float*)d_in[1];
    const float* qpos    = (const float*)d_in[2];
    const float* refpts  = (const float*)d_in[3];
    const float* W_val   = (const float*)d_in[4];
    const float* b_val   = (const float*)d_in[5];
    const float* W_off   = (const float*)d_in[6];
    const float* b_off   = (const float*)d_in[7];
    const float* W_attn  = (const float*)d_in[8];
    const float* b_attn  = (const float*)d_in[9];
    float* out = (float*)d_out;

    float *pv, *poff, *pattn;
    cudaGetSymbolAddress((void**)&pv, g_v);
    cudaGetSymbolAddress((void**)&poff, g_off);
    cudaGetSymbolAddress((void**)&pattn, g_attn);

    bf16 *qh, *ql, *vh, *vl, *wvh, *wvl, *woh, *wol, *wah, *wal;
    cudaGetSymbolAddress((void**)&qh, g_qh);
    cudaGetSymbolAddress((void**)&ql, g_ql);
    cudaGetSymbolAddress((void**)&vh, g_vh);
    cudaGetSymbolAddress((void**)&vl, g_vl);
    cudaGetSymbolAddress((void**)&wvh, g_wvh);
    cudaGetSymbolAddress((void**)&wvl, g_wvl);
    cudaGetSymbolAddress((void**)&woh, g_woh);
    cudaGetSymbolAddress((void**)&wol, g_wol);
    cudaGetSymbolAddress((void**)&wah, g_wah);
    cudaGetSymbolAddress((void**)&wal, g_wal);

    const int Mv = BS * NV;      // 39120
    const int Mq = BS * NQ;      // 20000

    cudaFuncSetAttribute(mma_gemm2, cudaFuncAttributeMaxDynamicSharedMemorySize,
                         SMEM_TOT);

    // conversions
    {
        int n4 = Mv * 256 / 4;
        conv_pair<<<(n4 + 255) / 256, 256>>>(value, nullptr, vh, vl, n4);
    }
    {
        int n4 = Mq * 256 / 4;
        conv_pair<<<(n4 + 255) / 256, 256>>>(query, qpos, qh, ql, n4);
    }
    conv_w_t<<<dim3(256 / 32, 8), 256>>>(W_val, wvh, wvl, 256);
    conv_w_t<<<dim3(256 / 32, 8), 256>>>(W_off, woh, wol, 256);
    conv_w_t<<<dim3(128 / 32, 8), 256>>>(W_attn, wah, wal, 128);

    // GEMMs
    mma_gemm2<<<dim3(2, (Mv + 127) / 128), 256, SMEM_TOT>>>(
        vh, vl, wvh, wvl, b_val, pv, Mv, 256, 1);
    mma_gemm2<<<dim3(2, (Mq + 127) / 128), 256, SMEM_TOT>>>(
        qh, ql, woh, wol, b_off, poff, Mq, 256, 0);
    mma_gemm2<<<dim3(1, (Mq + 127) / 128), 256, SMEM_TOT>>>(
        qh, ql, wah, wal, b_attn, pattn, Mq, 128, 0);

    // sampling + weighted sum
    {
        const int total_warps = BS * NQ * NHEAD;
        const int warps_per_block = 8;
        const int blocks = (total_warps + warps_per_block - 1) / warps_per_block;
        sample_kernel<<<blocks, warps_per_block * 32>>>(refpts, out);
    }
}

// round 8
// speedup vs baseline: 2.2344x; 1.2439x over previous
#include <cuda_runtime.h>
#include <cuda_bf16.h>
#include <math.h>
#include <stdint.h>

#define BS 2
#define NQ 10000
#define NV 19560
#define EMBED 256
#define NHEAD 8
#define HDIM 32

typedef __nv_bfloat16 bf16;

// Scratch (allocation-free rule: __device__ globals)
__device__ float g_v[(size_t)BS * NHEAD * NV * HDIM]; // (b, h, pos, d)
__device__ float g_off[(size_t)BS * NQ * 256];
__device__ float g_attn[(size_t)BS * NQ * 128];

// bf16 hi/lo split operands (precomputed once per call)
__device__ bf16 g_qh[(size_t)BS * NQ * 256];
__device__ bf16 g_ql[(size_t)BS * NQ * 256];
__device__ bf16 g_vh[(size_t)BS * NV * 256];
__device__ bf16 g_vl[(size_t)BS * NV * 256];
__device__ bf16 g_wvh[256 * 256], g_wvl[256 * 256];   // W_val^T  [n][k]
__device__ bf16 g_woh[256 * 256], g_wol[256 * 256];   // W_off^T  [n][k]
__device__ bf16 g_wah[128 * 256], g_wal[128 * 256];   // W_attn^T [n][k]

// ===========================================================================
// helpers
// ===========================================================================
__device__ __forceinline__ uint32_t smem_u32(const void* p) {
    uint32_t a;
    asm("{ .reg .u64 t; cvta.to.shared.u64 t, %1; cvt.u32.u64 %0, t; }"
        : "=r"(a) : "l"(p));
    return a;
}
__device__ __forceinline__ void cvt_hl(float x, bf16& h, bf16& l) {
    h = __float2bfloat16_rn(x);
    l = __float2bfloat16_rn(x - __bfloat162float(h));
}

#define CP16(dst, src) \
    asm volatile("cp.async.cg.shared.global [%0], [%1], 16;" \
                 :: "r"(dst), "l"(src))
#define CP_COMMIT() asm volatile("cp.async.commit_group;")
#define CP_WAIT(n)  asm volatile("cp.async.wait_group %0;" :: "n"(n))

#define LDSM_X4(r0, r1, r2, r3, addr) \
    asm volatile("ldmatrix.sync.aligned.m8n8.x4.shared.b16 {%0,%1,%2,%3}, [%4];" \
                 : "=r"(r0), "=r"(r1), "=r"(r2), "=r"(r3) : "r"(addr))

__device__ __forceinline__ void mma_bf16(float* c,
                                         uint32_t a0, uint32_t a1, uint32_t a2, uint32_t a3,
                                         uint32_t b0, uint32_t b1) {
    asm volatile(
        "mma.sync.aligned.m16n8k16.row.col.f32.bf16.bf16.f32 "
        "{%0,%1,%2,%3}, {%4,%5,%6,%7}, {%8,%9}, {%0,%1,%2,%3};"
        : "+f"(c[0]), "+f"(c[1]), "+f"(c[2]), "+f"(c[3])
        : "r"(a0), "r"(a1), "r"(a2), "r"(a3), "r"(b0), "r"(b1));
}

// ===========================================================================
// conversion kernels
// ===========================================================================
__global__ void conv_pair(const float* __restrict__ x, const float* __restrict__ x2,
                          bf16* __restrict__ hi, bf16* __restrict__ lo, int n4)
{
    const int i = blockIdx.x * blockDim.x + threadIdx.x;
    if (i >= n4) return;
    float4 v = ((const float4*)x)[i];
    if (x2) {
        float4 u = ((const float4*)x2)[i];
        v.x += u.x; v.y += u.y; v.z += u.z; v.w += u.w;
    }
    bf16 h[4], l[4];
    cvt_hl(v.x, h[0], l[0]); cvt_hl(v.y, h[1], l[1]);
    cvt_hl(v.z, h[2], l[2]); cvt_hl(v.w, h[3], l[3]);
    ((uint2*)hi)[i] = *(uint2*)h;
    ((uint2*)lo)[i] = *(uint2*)l;
}

// All three weights transposed in one launch: z selects the matrix.
__global__ void conv_w_t_all(const float* __restrict__ Wv,
                             const float* __restrict__ Wo,
                             const float* __restrict__ Wa,
                             bf16* __restrict__ vh, bf16* __restrict__ vl,
                             bf16* __restrict__ oh, bf16* __restrict__ ol,
                             bf16* __restrict__ ah, bf16* __restrict__ al)
{
    const float* W;
    bf16 *th, *tl;
    int N;
    if (blockIdx.z == 0)      { W = Wv; th = vh; tl = vl; N = 256; }
    else if (blockIdx.z == 1) { W = Wo; th = oh; tl = ol; N = 256; }
    else                      { W = Wa; th = ah; tl = al; N = 128; }
    if ((int)(blockIdx.x * 32) >= N) return;

    __shared__ float t[32][33];
    const int k0 = blockIdx.y * 32, n0 = blockIdx.x * 32;
    const int tx = threadIdx.x & 31, ty = threadIdx.x >> 5;  // 32 x 8
#pragma unroll
    for (int j = 0; j < 4; j++)
        t[ty + j * 8][tx] = W[(size_t)(k0 + ty + j * 8) * N + n0 + tx];
    __syncthreads();
#pragma unroll
    for (int j = 0; j < 4; j++) {
        const int n = n0 + ty + j * 8;
        const int k = k0 + tx;
        bf16 h, l;
        cvt_hl(t[tx][ty + j * 8], h, l);
        th[(size_t)n * 256 + k] = h;
        tl[(size_t)n * 256 + k] = l;
    }
}

// ===========================================================================
// bf16 3-term mma.sync GEMM with cp.async double buffering + ldmatrix.
// ===========================================================================
#define TSTR 40
#define TILE_B (128 * TSTR * 2)
#define BUF_B  (4 * TILE_B)
#define SMEM_TOT (2 * BUF_B)

__device__ __forceinline__ void load_chunk(uint32_t sb,
                                           const bf16* __restrict__ Ah_g,
                                           const bf16* __restrict__ Al_g,
                                           const bf16* __restrict__ Bh_g,
                                           const bf16* __restrict__ Bl_g,
                                           int m0, int n0, int M, int k0, int tid)
{
#pragma unroll
    for (int i = 0; i < 2; i++) {
        const int cid = tid + i * 256;
        const int row = cid >> 2;
        const int cp = cid & 3;
        int gm = m0 + row;
        if (gm >= M) gm = M - 1;
        const uint32_t doff = (uint32_t)(row * 80 + cp * 16);
        const size_t asrc = (size_t)gm * 256 + k0 + cp * 8;
        const size_t bsrc = (size_t)(n0 + row) * 256 + k0 + cp * 8;
        CP16(sb + doff,              Ah_g + asrc);
        CP16(sb + TILE_B + doff,     Al_g + asrc);
        CP16(sb + 2 * TILE_B + doff, Bh_g + bsrc);
        CP16(sb + 3 * TILE_B + doff, Bl_g + bsrc);
    }
}

__global__ __launch_bounds__(256)
void mma_gemm2(const bf16* __restrict__ Ah_g, const bf16* __restrict__ Al_g,
               const bf16* __restrict__ Bh_g, const bf16* __restrict__ Bl_g,
               const float* __restrict__ bias, float* __restrict__ C,
               int M, int N, int permuteV)
{
    extern __shared__ char smem[];
    const uint32_t sbase = smem_u32(smem);
    const int tid = threadIdx.x;
    const int wid = tid >> 5;
    const int lane = tid & 31;
    const int m0 = blockIdx.y * 128;
    const int n0 = blockIdx.x * 128;

    const int wm = wid >> 2;
    const int wn = wid & 3;
    const int grp = lane >> 2;
    const int qid = lane & 3;

    float acc[4][4][4];
#pragma unroll
    for (int i = 0; i < 4; i++)
#pragma unroll
        for (int j = 0; j < 4; j++)
#pragma unroll
            for (int r = 0; r < 4; r++) acc[i][j][r] = 0.f;

    const int mat = lane >> 3;
    const int arow_off = (lane & 7) + (mat & 1) * 8;
    const int akoff = (mat >> 1) * 16;
    const int brow_off = (lane & 7) + ((mat >> 1) & 1) * 8;
    const int bkoff = (mat & 1) * 16;

    load_chunk(sbase, Ah_g, Al_g, Bh_g, Bl_g, m0, n0, M, 0, tid);
    CP_COMMIT();

    const int NCH = 256 / 32;
#pragma unroll 1
    for (int c = 0; c < NCH; c++) {
        if (c + 1 < NCH) {
            load_chunk(sbase + ((c + 1) & 1) * BUF_B,
                       Ah_g, Al_g, Bh_g, Bl_g, m0, n0, M, (c + 1) * 32, tid);
            CP_COMMIT();
            CP_WAIT(1);
        } else {
            CP_WAIT(0);
        }
        __syncthreads();

        const uint32_t sA = sbase + (c & 1) * BUF_B;
        const uint32_t sAl = sA + TILE_B;
        const uint32_t sBh = sA + 2 * TILE_B;
        const uint32_t sBl = sA + 3 * TILE_B;

#pragma unroll
        for (int ks = 0; ks < 2; ks++) {
            const int kb = ks * 32;
            uint32_t ah[4][4], al[4][4], bh[4][2], bl[4][2];
#pragma unroll
            for (int tm = 0; tm < 4; tm++) {
                const uint32_t aaddr =
                    (uint32_t)((wm * 64 + tm * 16 + arow_off) * 80 + kb + akoff);
                LDSM_X4(ah[tm][0], ah[tm][1], ah[tm][2], ah[tm][3], sA + aaddr);
                LDSM_X4(al[tm][0], al[tm][1], al[tm][2], al[tm][3], sAl + aaddr);
            }
#pragma unroll
            for (int half = 0; half < 2; half++) {
                const uint32_t baddr =
                    (uint32_t)((wn * 32 + half * 16 + brow_off) * 80 + kb + bkoff);
                uint32_t t0, t1, t2, t3;
                LDSM_X4(t0, t1, t2, t3, sBh + baddr);
                bh[half * 2][0] = t0; bh[half * 2][1] = t1;
                bh[half * 2 + 1][0] = t2; bh[half * 2 + 1][1] = t3;
                LDSM_X4(t0, t1, t2, t3, sBl + baddr);
                bl[half * 2][0] = t0; bl[half * 2][1] = t1;
                bl[half * 2 + 1][0] = t2; bl[half * 2 + 1][1] = t3;
            }
#pragma unroll
            for (int tm = 0; tm < 4; tm++)
#pragma unroll
                for (int tn = 0; tn < 4; tn++) {
                    float* cc = acc[tm][tn];
                    mma_bf16(cc, ah[tm][0], ah[tm][1], ah[tm][2], ah[tm][3],
                             bh[tn][0], bh[tn][1]);
                    mma_bf16(cc, ah[tm][0], ah[tm][1], ah[tm][2], ah[tm][3],
                             bl[tn][0], bl[tn][1]);
                    mma_bf16(cc, al[tm][0], al[tm][1], al[tm][2], al[tm][3],
                             bh[tn][0], bh[tn][1]);
                }
        }
        __syncthreads();
    }

#pragma unroll
    for (int tm = 0; tm < 4; tm++) {
#pragma unroll
        for (int half = 0; half < 2; half++) {
            const int gm = m0 + wm * 64 + tm * 16 + grp + half * 8;
            if (gm >= M) continue;
#pragma unroll
            for (int tn = 0; tn < 4; tn++) {
                const int gn = n0 + wn * 32 + tn * 8 + qid * 2;
                float2 bsv = *(const float2*)(bias + gn);
                float2 o;
                o.x = acc[tm][tn][half * 2 + 0] + bsv.x;
                o.y = acc[tm][tn][half * 2 + 1] + bsv.y;
                if (permuteV) {
                    const int b = gm / NV;
                    const int pos = gm - b * NV;
                    const int h = gn >> 5, d = gn & 31;
                    *(float2*)(C + (((size_t)(b * NHEAD + h) * NV + pos) * HDIM + d)) = o;
                } else {
                    *(float2*)(C + (size_t)gm * N + gn) = o;
                }
            }
        }
    }
}

// ---------------------------------------------------------------------------
// Deformable sampling v3: one warp = one (b, q) x TWO heads.
//   half = lane>>4 selects head;  sl = lane&15 is BOTH the (level,point) slot
//   (softmax + coords, all 32 lanes busy) AND the channel-pair id: each lane
//   gathers float2 channels (2sl, 2sl+1) of its head.
// ---------------------------------------------------------------------------
__global__ void sample_kernel(const float* __restrict__ refpts,
                              float* __restrict__ out)
{
    const int gwarp = (blockIdx.x * blockDim.x + threadIdx.x) >> 5;
    const int lane = threadIdx.x & 31;
    const int total = BS * NQ * (NHEAD / 2);
    if (gwarp >= total) return;

    const int hp = gwarp & 3;             // head pair 0..3
    const int bq = gwarp >> 2;            // b*NQ + q
    const int b  = bq / NQ;
    const int half = lane >> 4;           // 0/1 -> head within pair
    const int sl = lane & 15;             // slot id & channel-pair id
    const int h = hp * 2 + half;

    const unsigned FULL = 0xFFFFFFFFu;

    // ---- softmax over 16 slots, within each 16-lane half ----
    float a = g_attn[(size_t)bq * 128 + h * 16 + sl];
    float amax = a;
#pragma unroll
    for (int s = 8; s > 0; s >>= 1)
        amax = fmaxf(amax, __shfl_xor_sync(FULL, amax, s));
    float e = __expf(a - amax);
    float esum = e;
#pragma unroll
    for (int s = 8; s > 0; s >>= 1)
        esum += __shfl_xor_sync(FULL, esum, s);
    const float wgt = e / esum;

    // ---- per-slot pixel coordinates ----
    const float LW[4] = {160.f, 80.f, 40.f, 20.f};
    const float LH[4] = {92.f, 46.f, 23.f, 12.f};
    const int l  = sl >> 2;
    const int pt = sl & 3;
    const float offx = g_off[(size_t)bq * 256 + h * 32 + l * 8 + pt * 2 + 0];
    const float offy = g_off[(size_t)bq * 256 + h * 32 + l * 8 + pt * 2 + 1];
    const float rx = refpts[(size_t)bq * 8 + pt * 2 + 0];
    const float ry = refpts[(size_t)bq * 8 + pt * 2 + 1];
    const float x = fmaf(rx + offx / LW[l], LW[l], -0.5f);
    const float y = fmaf(ry + offy / LH[l], LH[l], -0.5f);

    const int HH[4] = {92, 46, 23, 12};
    const int WW[4] = {160, 80, 40, 20};
    const int ST[4] = {0, 14720, 18400, 19320};

    // per-lane base: head plane + channel pair
    const float2* __restrict__ vp = (const float2*)
        (g_v + ((size_t)(b * NHEAD + h) * NV) * HDIM) + sl;

    float2 acc = make_float2(0.f, 0.f);
    const int hsel = lane & 16;           // shfl source offset for this half

#pragma unroll
    for (int p = 0; p < 16; p++) {
        const float xp = __shfl_sync(FULL, x, p | hsel);
        const float yp = __shfl_sync(FULL, y, p | hsel);
        const float wp = __shfl_sync(FULL, wgt, p | hsel);
        const int lv = p >> 2;
        const int Hl = HH[lv], Wl = WW[lv], base = ST[lv];

        const float x0f = floorf(xp), y0f = floorf(yp);
        const float wx1 = xp - x0f;
        const float wy1r = yp - y0f;
        const float wx0 = 1.f - wx1;
        const float wy1 = wy1r * wp;
        const float wy0 = (1.f - wy1r) * wp;
        const int x0 = (int)x0f, y0 = (int)y0f;

        const int idx00 = (base + y0 * Wl + x0) * 16;   // float2 units
        const bool vx0 = (unsigned)x0 < (unsigned)Wl;
        const bool vx1 = (unsigned)(x0 + 1) < (unsigned)Wl;
        const bool vy0 = (unsigned)y0 < (unsigned)Hl;
        const bool vy1 = (unsigned)(y0 + 1) < (unsigned)Hl;
        const int rstep = Wl * 16;

        if (vy0 & vx0) {
            const float2 v = __ldg(vp + idx00);
            const float cw = wy0 * wx0;
            acc.x = fmaf(v.x, cw, acc.x); acc.y = fmaf(v.y, cw, acc.y);
        }
        if (vy0 & vx1) {
            const float2 v = __ldg(vp + idx00 + 16);
            const float cw = wy0 * wx1;
            acc.x = fmaf(v.x, cw, acc.x); acc.y = fmaf(v.y, cw, acc.y);
        }
        if (vy1 & vx0) {
            const float2 v = __ldg(vp + idx00 + rstep);
            const float cw = wy1 * wx0;
            acc.x = fmaf(v.x, cw, acc.x); acc.y = fmaf(v.y, cw, acc.y);
        }
        if (vy1 & vx1) {
            const float2 v = __ldg(vp + idx00 + rstep + 16);
            const float cw = wy1 * wx1;
            acc.x = fmaf(v.x, cw, acc.x); acc.y = fmaf(v.y, cw, acc.y);
        }
    }

    ((float2*)(out + (size_t)bq * EMBED + h * HDIM))[sl] = acc;
}

// ---------------------------------------------------------------------------
extern "C" void kernel_launch(void* const* d_in, const int* in_sizes, int n_in,
                              void* d_out, int out_size)
{
    const float* query   = (const float*)d_in[0];
    const float* value   = (const float*)d_in[1];
    const float* qpos    = (const float*)d_in[2];
    const float* refpts  = (const float*)d_in[3];
    const float* W_val   = (const float*)d_in[4];
    const float* b_val   = (const float*)d_in[5];
    const float* W_off   = (const float*)d_in[6];
    const float* b_off   = (const float*)d_in[7];
    const float* W_attn  = (const float*)d_in[8];
    const float* b_attn  = (const float*)d_in[9];
    float* out = (float*)d_out;

    float *pv, *poff, *pattn;
    cudaGetSymbolAddress((void**)&pv, g_v);
    cudaGetSymbolAddress((void**)&poff, g_off);
    cudaGetSymbolAddress((void**)&pattn, g_attn);

    bf16 *qh, *ql, *vh, *vl, *wvh, *wvl, *woh, *wol, *wah, *wal;
    cudaGetSymbolAddress((void**)&qh, g_qh);
    cudaGetSymbolAddress((void**)&ql, g_ql);
    cudaGetSymbolAddress((void**)&vh, g_vh);
    cudaGetSymbolAddress((void**)&vl, g_vl);
    cudaGetSymbolAddress((void**)&wvh, g_wvh);
    cudaGetSymbolAddress((void**)&wvl, g_wvl);
    cudaGetSymbolAddress((void**)&woh, g_woh);
    cudaGetSymbolAddress((void**)&wol, g_wol);
    cudaGetSymbolAddress((void**)&wah, g_wah);
    cudaGetSymbolAddress((void**)&wal, g_wal);

    const int Mv = BS * NV;      // 39120
    const int Mq = BS * NQ;      // 20000

    cudaFuncSetAttribute(mma_gemm2, cudaFuncAttributeMaxDynamicSharedMemorySize,
                         SMEM_TOT);

    // conversions
    {
        int n4 = Mv * 256 / 4;
        conv_pair<<<(n4 + 255) / 256, 256>>>(value, nullptr, vh, vl, n4);
    }
    {
        int n4 = Mq * 256 / 4;
        conv_pair<<<(n4 + 255) / 256, 256>>>(query, qpos, qh, ql, n4);
    }
    conv_w_t_all<<<dim3(8, 8, 3), 256>>>(W_val, W_off, W_attn,
                                         wvh, wvl, woh, wol, wah, wal);

    // GEMMs
    mma_gemm2<<<dim3(2, (Mv + 127) / 128), 256, SMEM_TOT>>>(
        vh, vl, wvh, wvl, b_val, pv, Mv, 256, 1);
    mma_gemm2<<<dim3(2, (Mq + 127) / 128), 256, SMEM_TOT>>>(
        qh, ql, woh, wol, b_off, poff, Mq, 256, 0);
    mma_gemm2<<<dim3(1, (Mq + 127) / 128), 256, SMEM_TOT>>>(
        qh, ql, wah, wal, b_attn, pattn, Mq, 128, 0);

    // sampling + weighted sum (one warp per (b,q) x head-pair)
    {
        const int total_warps = BS * NQ * (NHEAD / 2);  // 80000
        const int warps_per_block = 8;
        const int blocks = (total_warps + warps_per_block - 1) / warps_per_block;
        sample_kernel<<<blocks, warps_per_block * 32>>>(refpts, out);
    }
}